// round 16
// baseline (speedup 1.0000x reference)
#include <cuda_runtime.h>
#include <cuda_fp16.h>
#include <math.h>
#include <stdint.h>

#define NN 50000
#define NE 640000
#define RR 8
#define DD 128
#define NRSEG (NN*RR)
#define NBLK ((NRSEG + 1023)/1024)

// ---------------- scratch (device globals; no allocations allowed) ----------
__device__ int      g_cnt[NRSEG];        // zero at load; self-zeroed by k_scatter
__device__ int      g_off[NRSEG];
__device__ int      g_cur[NRSEG];
__device__ unsigned long long g_tstat[NBLK];  // lookback flags; reset by k_scatter
__device__ unsigned g_ed[NE];            // packed (src<<16)|dst (UNSIGNED), CSR order
__device__ __half   g_xh[NN*DD];         // x pre-converted to half
__device__ __half   g_h[NN*DD];          // layer1 output (half)
__device__ __half   g_W1h[(RR+1)*DD*DD]; // [chunk][n][k-permuted] half
__device__ __half   g_W2h[(RR+1)*64*DD];

// k-permutation within each 16-group: slot order packs (2t,2t+1,2t+8,2t+9)
// adjacent so one LDS.64 yields both fp16-MMA fragments.
__device__ __forceinline__ int slot16(int c) {
    return ((c & 7) >> 1)*4 + (c & 1) + ((c & 8) >> 3)*2;
}

#define CP_ASYNC16(smem_u32, gptr) \
    asm volatile("cp.async.cg.shared.global [%0], [%1], 16;" \
                 :: "r"(smem_u32), "l"(gptr) : "memory")
#define CP_COMMIT()  asm volatile("cp.async.commit_group;" ::: "memory")
#define CP_WAIT0()   asm volatile("cp.async.wait_group 0;" ::: "memory")

// ---------------- prelude: hist + weight cvt/permute + x cvt fused -----------
// seg ordering is RELATION-MAJOR: seg = rel*NN + node, so each row-block x rel
// owns one contiguous edge slice sorted by dst.
__global__ void k_pre(const int* __restrict__ dst, const int* __restrict__ typ,
                      const float* __restrict__ x,
                      const float* __restrict__ W1, const float* __restrict__ r1,
                      const float* __restrict__ W2, const float* __restrict__ r2) {
    const int HB = (NE + 255)/256;
    const int T1 = ((RR+1)*DD*DD + 255)/256;
    const int T2 = ((RR+1)*64*DD + 255)/256;
    int b = blockIdx.x;
    if (b < HB) {
        int e = b*256 + threadIdx.x;
        if (e < NE) atomicAdd(&g_cnt[typ[e]*NN + dst[e]], 1);
    } else if (b < HB + T1) {
        int idx = (b - HB)*256 + threadIdx.x;
        if (idx < (RR+1)*DD*DD) {
            int chunk = idx / (DD*DD);
            int rem   = idx - chunk*(DD*DD);
            int n = rem >> 7, k = rem & 127;
            float v = (chunk < RR) ? W1[(size_t)chunk*DD*DD + (size_t)k*DD + n]
                                   : r1[(size_t)k*DD + n];
            g_W1h[(size_t)chunk*DD*DD + n*DD + (k & ~15) + slot16(k & 15)] =
                __float2half_rn(v);
        }
    } else if (b < HB + T1 + T2) {
        int idx = (b - HB - T1)*256 + threadIdx.x;
        if (idx < (RR+1)*64*DD) {
            int chunk = idx / (64*DD);
            int rem   = idx - chunk*(64*DD);
            int n = rem >> 7, k = rem & 127;
            float v = (chunk < RR) ? W2[(size_t)chunk*DD*64 + (size_t)k*64 + n]
                                   : r2[(size_t)k*64 + n];
            g_W2h[(size_t)chunk*64*DD + n*DD + (k & ~15) + slot16(k & 15)] =
                __float2half_rn(v);
        }
    } else {
        // x -> half, 4 floats per thread
        int idx = (b - HB - T1 - T2)*256 + threadIdx.x;
        if (idx < NN*DD/4) {
            float4 xv = reinterpret_cast<const float4*>(x)[idx];
            __half2* o = reinterpret_cast<__half2*>(g_xh) + idx*2;
            o[0] = __floats2half2_rn(xv.x, xv.y);
            o[1] = __floats2half2_rn(xv.z, xv.w);
        }
    }
}

// ---------------- single-pass decoupled-lookback scan ------------------------
__global__ void __launch_bounds__(1024)
k_scan() {
    __shared__ int swarp[32];
    __shared__ int s_prefix;
    const int tid  = threadIdx.x;
    const int lane = tid & 31;
    const int wid  = tid >> 5;
    const int b    = blockIdx.x;
    const int i    = b*1024 + tid;

    int v = (i < NRSEG) ? g_cnt[i] : 0;

    int x = v;
    #pragma unroll
    for (int d = 1; d < 32; d <<= 1) {
        int t = __shfl_up_sync(0xffffffffu, x, d);
        if (lane >= d) x += t;
    }
    if (lane == 31) swarp[wid] = x;
    __syncthreads();
    if (wid == 0) {
        int y = swarp[lane];
        #pragma unroll
        for (int d = 1; d < 32; d <<= 1) {
            int t = __shfl_up_sync(0xffffffffu, y, d);
            if (lane >= d) y += t;
        }
        swarp[lane] = y;
    }
    __syncthreads();
    int incl = x + ((wid > 0) ? swarp[wid-1] : 0);
    int blocksum = swarp[31];

    if (tid == 0) {
        if (b == 0) {
            atomicExch(&g_tstat[0], (2ULL<<32) | (unsigned)blocksum);
            s_prefix = 0;
        } else {
            atomicExch(&g_tstat[b], (1ULL<<32) | (unsigned)blocksum);
            int run = 0;
            int j = b - 1;
            while (true) {
                unsigned long long f = atomicAdd(&g_tstat[j], 0ULL);
                unsigned st = (unsigned)(f >> 32);
                if (st == 0) { __nanosleep(40); continue; }
                run += (int)(unsigned)(f & 0xffffffffu);
                if (st == 2) break;
                --j;
            }
            atomicExch(&g_tstat[b], (2ULL<<32) | (unsigned)(run + blocksum));
            s_prefix = run;
        }
    }
    __syncthreads();
    if (i < NRSEG) {
        int o = s_prefix + incl - v;
        g_off[i] = o;
        g_cur[i] = o;
    }
}

__global__ void k_scatter(const int* __restrict__ src, const int* __restrict__ dst,
                          const int* __restrict__ typ) {
    int e = blockIdx.x*blockDim.x + threadIdx.x;
    if (e < NE) {
        int d = dst[e];
        int seg = typ[e]*NN + d;
        int pos = atomicAdd(&g_cur[seg], 1);
        g_ed[pos] = ((unsigned)src[e] << 16) | (unsigned)d;   // both < 65536
    }
    if (e < NRSEG) g_cnt[e] = 0;
    if (e < NBLK)  g_tstat[e] = 0ULL;
}

// ---------------- fused aggregate + GEMM layer (fp16 MMA) -------------------
__device__ __forceinline__ void mma_f16(float& c0, float& c1, float& c2, float& c3,
                                        uint32_t a0, uint32_t a1, uint32_t a2, uint32_t a3,
                                        uint32_t b0, uint32_t b1) {
    asm volatile(
        "mma.sync.aligned.m16n8k16.row.col.f32.f16.f16.f32 "
        "{%0,%1,%2,%3},{%4,%5,%6,%7},{%8,%9},{%0,%1,%2,%3};"
        : "+f"(c0), "+f"(c1), "+f"(c2), "+f"(c3)
        : "r"(a0), "r"(a1), "r"(a2), "r"(a3), "r"(b0), "r"(b1));
}

__device__ __forceinline__ uint32_t pack_h2(float x, float y) {
    __half2 h = __floats2half2_rn(x, y);
    return *reinterpret_cast<uint32_t*>(&h);
}
__device__ __forceinline__ float2 unpack_h2(uint32_t u) {
    __half2 h = *reinterpret_cast<__half2*>(&u);
    return __half22float2(h);
}
__device__ __forceinline__ uint32_t hadd2_u32(uint32_t a, uint32_t b) {
    __half2 r = __hadd2(*reinterpret_cast<__half2*>(&a),
                        *reinterpret_cast<__half2*>(&b));
    return *reinterpret_cast<uint32_t*>(&r);
}

// CTA = 128 nodes, 512 threads, 16 warps, 2 CTAs/SM (32 warps/SM, occ 50%).
// Node features half; sB double-buffered via cp.async. Gather: pair {w, w+8}
// produces the 16 rows both warps' MMA reads (grow = 16*(w&7) + 8*(w>>3));
// warp's 8 rows split into TWO independent 4-row run-chains, interleaved with
// warp-uniform guards -> MLP >= 2 and half-length chains. Edge records packed
// unsigned (src<<16)|dst, staged once per chunk (fallback for long slices).
// MMA: warp w computes rows [16*(w&7), +16) x cols [(w>>3)*O/2, +O/2).
template<int O, bool SIG, typename OutT>
__global__ void __launch_bounds__(512, 2)
k_layer(const __half* __restrict__ in,
        const __half* __restrict__ Wh,    // [9][O][DD] half, k-permuted
        const float* __restrict__ bias,
        OutT* __restrict__ out) {
    constexpr int TM = 128;
    constexpr int NT = 512;
    constexpr int WP = 72;     // half2 words per row (64 data + 8 pad)
    constexpr int O2 = O/2;

    extern __shared__ uint32_t smem[];
    uint32_t* sA = smem;                 // TM * WP
    uint32_t* sB0 = smem + TM*WP;        // O * WP (buffer 0)
    uint32_t* sB1 = sB0 + O*WP;          // O * WP (buffer 1)
    const uint32_t smem_u32 = (uint32_t)__cvta_generic_to_shared(smem);

    const int tid  = threadIdx.x;
    const int lane = tid & 31;
    const int wid  = tid >> 5;
    const int tile = blockIdx.x * TM;

    float acc[O2/8][4];
    #pragma unroll
    for (int n8 = 0; n8 < O2/8; ++n8) {
        acc[n8][0] = 0.f; acc[n8][1] = 0.f; acc[n8][2] = 0.f; acc[n8][3] = 0.f;
    }

    const int g  = lane >> 2;
    const int tg = lane & 3;
    const int mrow = (wid & 7) * 16;              // MMA row block
    const int ncol = (wid >> 3) * O2;             // MMA col block
    const int grow = (wid & 7)*16 + (wid >> 3)*8; // gather rows (pair covers mrow..+16)
    const int pbar = 1 + (wid & 7);               // pair barrier id
    // lane's two half2 store slots (natural cols 4l..4l+3 under permutation)
    const int wbase = (lane >> 2)*8 + ((lane & 1) << 2) + ((lane & 2) >> 1);
    const __half* in_l = in + (lane << 2);    // lane-fixed column base

    // ---- cp.async fill helper (16B units): row n = u>>4, sub = u&15
    auto fill_sB = [&](int bufsel, int r) {
        const __half* Wp = Wh + (size_t)r*O*DD;
        uint32_t sbase = smem_u32 + (TM*WP + bufsel*O*WP)*4;
        #pragma unroll
        for (int u = tid; u < O*16; u += NT) {
            int n = u >> 4, sub = u & 15;
            CP_ASYNC16(sbase + (n*WP + sub*4)*4, Wp + n*DD + sub*8);
        }
        CP_COMMIT();
    };

    // prologue: prefetch chunk 0 into buffer 0
    fill_sB(0, 0);
    int cur = 0;

    for (int r = 0; r < RR + 1; ++r) {
        CP_WAIT0();
        __syncthreads();   // sB[cur] visible; prev MMA done with sA & sB[cur^1]
        if (r < RR) fill_sB(cur ^ 1, r + 1);   // overlap with gather + MMA

        // ================= gather: warp -> 8 rows, dual run-chains ===========
        if (r < RR) {
            // lane l (l<=8) holds boundary offset for row grow+l
            int bidx = r*NN + min(tile + grow + min(lane, 8), NN);
            int offv = (bidx < NRSEG) ? g_off[bidx] : NE;
            int es   = __shfl_sync(0xffffffffu, offv, 0);
            int emid = __shfl_sync(0xffffffffu, offv, 4);
            int ee   = __shfl_sync(0xffffffffu, offv, 8);
            int len  = ee - es;

            if (len <= 32) {
                // stage whole slice: ONE coalesced LDG.32
                unsigned rec = 0u;
                if (lane < len) rec = g_ed[es + lane];
                const int eA = emid - es;     // chain A: [0,eA), chain B: [eA,len)
                int iA = 0, iB = eA;
                uint32_t vA0=0u, vA1=0u, vB0=0u, vB1=0u;
                int rowA = -1, rowB = -1;
                const int n = max(eA, len - eA);
                for (int t = 0; t < n; ++t) {
                    if (iA < eA) {              // warp-uniform guard
                        unsigned p = __shfl_sync(0xffffffffu, rec, iA);
                        const uint2 u = *reinterpret_cast<const uint2*>(
                            in_l + (size_t)(p >> 16)*DD);
                        int row = (int)(p & 0xFFFFu);
                        bool fresh = (row != rowA);
                        rowA = row;
                        vA0 = fresh ? u.x : hadd2_u32(vA0, u.x);
                        vA1 = fresh ? u.y : hadd2_u32(vA1, u.y);
                        int rw = (rowA - tile)*WP;
                        sA[rw + wbase]     = vA0;
                        sA[rw + wbase + 2] = vA1;
                    }
                    if (iB < len) {             // warp-uniform guard
                        unsigned p = __shfl_sync(0xffffffffu, rec, iB);
                        const uint2 u = *reinterpret_cast<const uint2*>(
                            in_l + (size_t)(p >> 16)*DD);
                        int row = (int)(p & 0xFFFFu);
                        bool fresh = (row != rowB);
                        rowB = row;
                        vB0 = fresh ? u.x : hadd2_u32(vB0, u.x);
                        vB1 = fresh ? u.y : hadd2_u32(vB1, u.y);
                        int rw = (rowB - tile)*WP;
                        sA[rw + wbase]     = vB0;
                        sA[rw + wbase + 2] = vB1;
                    }
                    ++iA; ++iB;
                }
            } else {
                // rare: long slice — batched single chain
                uint32_t v0=0u, v1=0u;
                int currow = -1;
                for (int base = es; base < ee; base += 32) {
                    const int m = min(ee - base, 32);
                    unsigned rec = 0u;
                    if (lane < m) rec = g_ed[base + lane];
                    #pragma unroll 4
                    for (int j = 0; j < m; ++j) {
                        unsigned p = __shfl_sync(0xffffffffu, rec, j);
                        const uint2 u = *reinterpret_cast<const uint2*>(
                            in_l + (size_t)(p >> 16)*DD);
                        int row = (int)(p & 0xFFFFu);
                        bool fresh = (row != currow);
                        currow = row;
                        v0 = fresh ? u.x : hadd2_u32(v0, u.x);
                        v1 = fresh ? u.y : hadd2_u32(v1, u.y);
                        int rw = (currow - tile)*WP;
                        sA[rw + wbase]     = v0;
                        sA[rw + wbase + 2] = v1;
                    }
                }
            }

            // post-pass: c==0 -> zero row slots; c>1 -> scale by 1/c (fp32)
            #pragma unroll
            for (int i = 0; i < 8; ++i) {
                int c = __shfl_sync(0xffffffffu, offv, i+1)
                      - __shfl_sync(0xffffffffu, offv, i);
                int idx = (grow+i)*WP + wbase;
                if (c == 0) {
                    sA[idx] = 0u; sA[idx+2] = 0u;
                } else if (c > 1) {
                    float inv = 1.f/(float)c;
                    float2 u0 = unpack_h2(sA[idx]);
                    float2 u1 = unpack_h2(sA[idx+2]);
                    sA[idx]   = pack_h2(u0.x*inv, u0.y*inv);
                    sA[idx+2] = pack_h2(u1.x*inv, u1.y*inv);
                }
            }
        } else {
            // root chunk: direct half copy of input tile
            #pragma unroll
            for (int ii = 0; ii < 8; ++ii) {
                int node = tile + grow + ii;
                uint2 u = make_uint2(0u, 0u);
                if (node < NN)
                    u = *reinterpret_cast<const uint2*>(
                        in_l + (size_t)node*DD);
                int idx = (grow+ii)*WP + wbase;
                sA[idx]   = u.x;
                sA[idx+2] = u.y;
            }
        }
        // pair-scoped barrier: warps w and w+8 produced rows [mrow, mrow+16)
        asm volatile("bar.sync %0, 64;" :: "r"(pbar) : "memory");

        // ================= MMA (fp16, fp32 accum) =================
        const uint32_t* sBc = (cur == 0) ? sB0 : sB1;
        #pragma unroll
        for (int k16 = 0; k16 < DD/16; ++k16) {
            const uint2 aLo = *reinterpret_cast<const uint2*>(
                &sA[(mrow + g    )*WP + k16*8 + tg*2]);   // (a0, a2)
            const uint2 aHi = *reinterpret_cast<const uint2*>(
                &sA[(mrow + g + 8)*WP + k16*8 + tg*2]);   // (a1, a3)
            #pragma unroll
            for (int n8 = 0; n8 < O2/8; ++n8) {
                const uint2 bb = *reinterpret_cast<const uint2*>(
                    &sBc[(ncol + n8*8 + g)*WP + k16*8 + tg*2]);  // (b0, b1)
                mma_f16(acc[n8][0], acc[n8][1], acc[n8][2], acc[n8][3],
                        aLo.x, aHi.x, aLo.y, aHi.y, bb.x, bb.y);
            }
        }
        cur ^= 1;
    }

    // ---- epilogue: bias (+ sigmoid), write out
    const int r0 = tile + mrow + g;
    const int r1 = r0 + 8;
    #pragma unroll
    for (int n8 = 0; n8 < O2/8; ++n8) {
        int c0 = ncol + n8*8 + 2*tg;
        int c1 = c0 + 1;
        float bz0 = bias[c0], bz1 = bias[c1];
        float v00 = acc[n8][0] + bz0;
        float v01 = acc[n8][1] + bz1;
        float v10 = acc[n8][2] + bz0;
        float v11 = acc[n8][3] + bz1;
        if (SIG) {
            v00 = 1.f/(1.f + __expf(-v00));
            v01 = 1.f/(1.f + __expf(-v01));
            v10 = 1.f/(1.f + __expf(-v10));
            v11 = 1.f/(1.f + __expf(-v11));
        }
        if (sizeof(OutT) == 2) {   // half2 pair store (c0 even)
            if (r0 < NN) *reinterpret_cast<__half2*>(
                (__half*)out + (size_t)r0*O + c0) = __floats2half2_rn(v00, v01);
            if (r1 < NN) *reinterpret_cast<__half2*>(
                (__half*)out + (size_t)r1*O + c0) = __floats2half2_rn(v10, v11);
        } else {
            if (r0 < NN) { ((float*)out)[(size_t)r0*O + c0] = v00;
                           ((float*)out)[(size_t)r0*O + c1] = v01; }
            if (r1 < NN) { ((float*)out)[(size_t)r1*O + c0] = v10;
                           ((float*)out)[(size_t)r1*O + c1] = v11; }
        }
    }
}

// ---------------- launch ----------------------------------------------------
extern "C" void kernel_launch(void* const* d_in, const int* in_sizes, int n_in,
                              void* d_out, int out_size) {
    const float* x    = (const float*)d_in[0];
    const int*   esrc = (const int*)  d_in[1];
    const int*   edst = (const int*)  d_in[2];
    const int*   etyp = (const int*)  d_in[3];
    const float* W1   = (const float*)d_in[4];
    const float* r1   = (const float*)d_in[5];
    const float* b1   = (const float*)d_in[6];
    const float* W2   = (const float*)d_in[7];
    const float* r2   = (const float*)d_in[8];
    const float* b2   = (const float*)d_in[9];
    float* out = (float*)d_out;

    constexpr int SMEM_L1 = (128 + 2*128) * 72 * 4;  // 110592 B -> 2 CTAs/SM
    constexpr int SMEM_L2 = (128 + 2* 64) * 72 * 4;  //  73728 B -> 2 CTAs/SM
    cudaFuncSetAttribute((const void*)k_layer<128,false,__half>,
                         cudaFuncAttributeMaxDynamicSharedMemorySize, SMEM_L1);
    cudaFuncSetAttribute((const void*)k_layer< 64,true ,float >,
                         cudaFuncAttributeMaxDynamicSharedMemorySize, SMEM_L2);

    void* p = nullptr;
    cudaGetSymbolAddress(&p, g_xh);  __half* xh  = (__half*)p;
    cudaGetSymbolAddress(&p, g_h);   __half* h   = (__half*)p;
    cudaGetSymbolAddress(&p, g_W1h); __half* w1h = (__half*)p;
    cudaGetSymbolAddress(&p, g_W2h); __half* w2h = (__half*)p;

    const int HB = (NE + 255)/256;
    const int T1 = ((RR+1)*DD*DD + 255)/256;
    const int T2 = ((RR+1)*64*DD + 255)/256;
    const int XC = (NN*DD/4 + 255)/256;
    k_pre    <<<HB + T1 + T2 + XC, 256>>>(edst, etyp, x, W1, r1, W2, r2); // launch 0
    k_scan   <<<NBLK,             1024>>>();                               // launch 1
    k_scatter<<<(NE+255)/256,      256>>>(esrc, edst, etyp);               // launch 2

    k_layer<128,false,__half><<<(NN+127)/128, 512, SMEM_L1>>>(xh, w1h, b1, h);   // launch 3
    k_layer< 64,true ,float ><<<(NN+127)/128, 512, SMEM_L2>>>(h,  w2h, b2, out); // launch 4
}

// round 17
// speedup vs baseline: 1.0621x; 1.0621x over previous
#include <cuda_runtime.h>
#include <cuda_fp16.h>
#include <math.h>
#include <stdint.h>

#define NN 50000
#define NE 640000
#define RR 8
#define DD 128
#define NRSEG (NN*RR)
#define NBLK ((NRSEG + 1023)/1024)

// ---------------- scratch (device globals; no allocations allowed) ----------
__device__ int      g_cnt[NRSEG];        // zero at load; self-zeroed by k_scatter
__device__ int      g_off[NRSEG];
__device__ int      g_cur[NRSEG];
__device__ unsigned long long g_tstat[NBLK];  // lookback flags; reset by k_scatter
__device__ unsigned g_ed[NE];            // packed (src<<16)|dst (unsigned), CSR order
__device__ __half   g_xh[NN*DD];         // x pre-converted to half
__device__ __half   g_h[NN*DD];          // layer1 output (half)
__device__ __half   g_W1h[(RR+1)*DD*DD]; // [chunk][n][k-permuted] half
__device__ __half   g_W2h[(RR+1)*64*DD];

// k-permutation within each 16-group: slot order packs (2t,2t+1,2t+8,2t+9)
// adjacent so one LDS.64 yields both fp16-MMA fragments.
__device__ __forceinline__ int slot16(int c) {
    return ((c & 7) >> 1)*4 + (c & 1) + ((c & 8) >> 3)*2;
}

#define CP_ASYNC16(smem_u32, gptr) \
    asm volatile("cp.async.cg.shared.global [%0], [%1], 16;" \
                 :: "r"(smem_u32), "l"(gptr) : "memory")
#define CP_COMMIT()  asm volatile("cp.async.commit_group;" ::: "memory")
#define CP_WAIT0()   asm volatile("cp.async.wait_group 0;" ::: "memory")

// ---------------- prelude: hist + weight cvt/permute + x cvt fused -----------
// seg ordering is RELATION-MAJOR: seg = rel*NN + node, so each row-block x rel
// owns one contiguous edge slice sorted by dst.
__global__ void k_pre(const int* __restrict__ dst, const int* __restrict__ typ,
                      const float* __restrict__ x,
                      const float* __restrict__ W1, const float* __restrict__ r1,
                      const float* __restrict__ W2, const float* __restrict__ r2) {
    const int HB = (NE + 255)/256;
    const int T1 = ((RR+1)*DD*DD + 255)/256;
    const int T2 = ((RR+1)*64*DD + 255)/256;
    int b = blockIdx.x;
    if (b < HB) {
        int e = b*256 + threadIdx.x;
        if (e < NE) atomicAdd(&g_cnt[typ[e]*NN + dst[e]], 1);
    } else if (b < HB + T1) {
        int idx = (b - HB)*256 + threadIdx.x;
        if (idx < (RR+1)*DD*DD) {
            int chunk = idx / (DD*DD);
            int rem   = idx - chunk*(DD*DD);
            int n = rem >> 7, k = rem & 127;
            float v = (chunk < RR) ? W1[(size_t)chunk*DD*DD + (size_t)k*DD + n]
                                   : r1[(size_t)k*DD + n];
            g_W1h[(size_t)chunk*DD*DD + n*DD + (k & ~15) + slot16(k & 15)] =
                __float2half_rn(v);
        }
    } else if (b < HB + T1 + T2) {
        int idx = (b - HB - T1)*256 + threadIdx.x;
        if (idx < (RR+1)*64*DD) {
            int chunk = idx / (64*DD);
            int rem   = idx - chunk*(64*DD);
            int n = rem >> 7, k = rem & 127;
            float v = (chunk < RR) ? W2[(size_t)chunk*DD*64 + (size_t)k*64 + n]
                                   : r2[(size_t)k*64 + n];
            g_W2h[(size_t)chunk*64*DD + n*DD + (k & ~15) + slot16(k & 15)] =
                __float2half_rn(v);
        }
    } else {
        // x -> half, 4 floats per thread
        int idx = (b - HB - T1 - T2)*256 + threadIdx.x;
        if (idx < NN*DD/4) {
            float4 xv = reinterpret_cast<const float4*>(x)[idx];
            __half2* o = reinterpret_cast<__half2*>(g_xh) + idx*2;
            o[0] = __floats2half2_rn(xv.x, xv.y);
            o[1] = __floats2half2_rn(xv.z, xv.w);
        }
    }
}

// ---------------- single-pass decoupled-lookback scan ------------------------
__global__ void __launch_bounds__(1024)
k_scan() {
    __shared__ int swarp[32];
    __shared__ int s_prefix;
    const int tid  = threadIdx.x;
    const int lane = tid & 31;
    const int wid  = tid >> 5;
    const int b    = blockIdx.x;
    const int i    = b*1024 + tid;

    int v = (i < NRSEG) ? g_cnt[i] : 0;

    int x = v;
    #pragma unroll
    for (int d = 1; d < 32; d <<= 1) {
        int t = __shfl_up_sync(0xffffffffu, x, d);
        if (lane >= d) x += t;
    }
    if (lane == 31) swarp[wid] = x;
    __syncthreads();
    if (wid == 0) {
        int y = swarp[lane];
        #pragma unroll
        for (int d = 1; d < 32; d <<= 1) {
            int t = __shfl_up_sync(0xffffffffu, y, d);
            if (lane >= d) y += t;
        }
        swarp[lane] = y;
    }
    __syncthreads();
    int incl = x + ((wid > 0) ? swarp[wid-1] : 0);
    int blocksum = swarp[31];

    if (tid == 0) {
        if (b == 0) {
            atomicExch(&g_tstat[0], (2ULL<<32) | (unsigned)blocksum);
            s_prefix = 0;
        } else {
            atomicExch(&g_tstat[b], (1ULL<<32) | (unsigned)blocksum);
            int run = 0;
            int j = b - 1;
            while (true) {
                unsigned long long f = atomicAdd(&g_tstat[j], 0ULL);
                unsigned st = (unsigned)(f >> 32);
                if (st == 0) { __nanosleep(40); continue; }
                run += (int)(unsigned)(f & 0xffffffffu);
                if (st == 2) break;
                --j;
            }
            atomicExch(&g_tstat[b], (2ULL<<32) | (unsigned)(run + blocksum));
            s_prefix = run;
        }
    }
    __syncthreads();
    if (i < NRSEG) {
        int o = s_prefix + incl - v;
        g_off[i] = o;
        g_cur[i] = o;
    }
}

__global__ void k_scatter(const int* __restrict__ src, const int* __restrict__ dst,
                          const int* __restrict__ typ) {
    int e = blockIdx.x*blockDim.x + threadIdx.x;
    if (e < NE) {
        int d = dst[e];
        int seg = typ[e]*NN + d;
        int pos = atomicAdd(&g_cur[seg], 1);
        g_ed[pos] = ((unsigned)src[e] << 16) | (unsigned)d;   // both < 65536
    }
    if (e < NRSEG) g_cnt[e] = 0;
    if (e < NBLK)  g_tstat[e] = 0ULL;
}

// ---------------- fused aggregate + GEMM layer (fp16 MMA) -------------------
__device__ __forceinline__ void mma_f16(float& c0, float& c1, float& c2, float& c3,
                                        uint32_t a0, uint32_t a1, uint32_t a2, uint32_t a3,
                                        uint32_t b0, uint32_t b1) {
    asm volatile(
        "mma.sync.aligned.m16n8k16.row.col.f32.f16.f16.f32 "
        "{%0,%1,%2,%3},{%4,%5,%6,%7},{%8,%9},{%0,%1,%2,%3};"
        : "+f"(c0), "+f"(c1), "+f"(c2), "+f"(c3)
        : "r"(a0), "r"(a1), "r"(a2), "r"(a3), "r"(b0), "r"(b1));
}

__device__ __forceinline__ uint32_t pack_h2(float x, float y) {
    __half2 h = __floats2half2_rn(x, y);
    return *reinterpret_cast<uint32_t*>(&h);
}
__device__ __forceinline__ float2 unpack_h2(uint32_t u) {
    __half2 h = *reinterpret_cast<__half2*>(&u);
    return __half22float2(h);
}
__device__ __forceinline__ uint32_t hadd2_u32(uint32_t a, uint32_t b) {
    __half2 r = __hadd2(*reinterpret_cast<__half2*>(&a),
                        *reinterpret_cast<__half2*>(&b));
    return *reinterpret_cast<uint32_t*>(&r);
}

// CTA = 128 nodes, 512 threads, 16 warps, 2 CTAs/SM (32 warps/SM, occ 50%).
// Node features half; sB double-buffered via cp.async. Gather: pair {w, w+8}
// produces the 16 rows both warps' MMA reads (grow = 16*(w&7) + 8*(w>>3)).
// HALF-WARP-PER-ROW: lanes 0-15 gather rows [grow, grow+4), lanes 16-31 rows
// [grow+4, grow+8); each lane holds 16B of the row, so ONE LDG.128 carries two
// rows' loads (structural MLP=2) and per-edge instructions halve. Divergence
// handles unequal half lengths; shfl uses per-half masks (width 16).
// MMA: warp w computes rows [16*(w&7), +16) x cols [(w>>3)*O/2, +O/2).
template<int O, bool SIG, typename OutT>
__global__ void __launch_bounds__(512, 2)
k_layer(const __half* __restrict__ in,
        const __half* __restrict__ Wh,    // [9][O][DD] half, k-permuted
        const float* __restrict__ bias,
        OutT* __restrict__ out) {
    constexpr int TM = 128;
    constexpr int NT = 512;
    constexpr int WP = 72;     // half2 words per row (64 data + 8 pad)
    constexpr int O2 = O/2;

    extern __shared__ uint32_t smem[];
    uint32_t* sA = smem;                 // TM * WP
    uint32_t* sB0 = smem + TM*WP;        // O * WP (buffer 0)
    uint32_t* sB1 = sB0 + O*WP;          // O * WP (buffer 1)
    const uint32_t smem_u32 = (uint32_t)__cvta_generic_to_shared(smem);

    const int tid  = threadIdx.x;
    const int lane = tid & 31;
    const int wid  = tid >> 5;
    const int tile = blockIdx.x * TM;

    float acc[O2/8][4];
    #pragma unroll
    for (int n8 = 0; n8 < O2/8; ++n8) {
        acc[n8][0] = 0.f; acc[n8][1] = 0.f; acc[n8][2] = 0.f; acc[n8][3] = 0.f;
    }

    const int g  = lane >> 2;
    const int tg = lane & 3;
    const int mrow = (wid & 7) * 16;              // MMA row block
    const int ncol = (wid >> 3) * O2;             // MMA col block
    const int grow = (wid & 7)*16 + (wid >> 3)*8; // gather rows (pair covers mrow..+16)
    const int pbar = 1 + (wid & 7);               // pair barrier id
    // half-warp gather geometry
    const int hl      = lane & 15;                // half-lane
    const int halfsel = lane >> 4;                // 0: rows 0-3, 1: rows 4-7
    const unsigned hmask = 0xFFFFu << (lane & 16);
    const int wslot = (hl >> 1)*8 + (hl & 1);     // row word base; +{0,2,4,6}
    const __half* in_h = in + hl*8;               // lane-fixed 16B column offset

    // ---- cp.async fill helper (16B units): row n = u>>4, sub = u&15
    auto fill_sB = [&](int bufsel, int r) {
        const __half* Wp = Wh + (size_t)r*O*DD;
        uint32_t sbase = smem_u32 + (TM*WP + bufsel*O*WP)*4;
        #pragma unroll
        for (int u = tid; u < O*16; u += NT) {
            int n = u >> 4, sub = u & 15;
            CP_ASYNC16(sbase + (n*WP + sub*4)*4, Wp + n*DD + sub*8);
        }
        CP_COMMIT();
    };

    // prologue: prefetch chunk 0 into buffer 0
    fill_sB(0, 0);
    int cur = 0;

    for (int r = 0; r < RR + 1; ++r) {
        CP_WAIT0();
        __syncthreads();   // sB[cur] visible; prev MMA done with sA & sB[cur^1]
        if (r < RR) fill_sB(cur ^ 1, r + 1);   // overlap with gather + MMA

        // ================= gather: half-warp -> 4 rows =================
        if (r < RR) {
            // lane l (l<=8) holds boundary offset for row grow+l
            int bidx = r*NN + min(tile + grow + min(lane, 8), NN);
            int offv = (bidx < NRSEG) ? g_off[bidx] : NE;
            int sh = __shfl_sync(0xffffffffu, offv, halfsel*4);      // half start
            int eh = __shfl_sync(0xffffffffu, offv, halfsel*4 + 4);  // half end
            int lenH = eh - sh;

            uint4 v = make_uint4(0u,0u,0u,0u);
            int currow = -1;
            for (int off = 0; off < lenH; off += 16) {
                const int m = min(lenH - off, 16);
                // stage up to 16 edge records per half: ONE LDG.32
                unsigned rec = 0u;
                if (off + hl < lenH) rec = g_ed[sh + off + hl];
                #pragma unroll 4
                for (int j = 0; j < m; ++j) {
                    unsigned p = __shfl_sync(hmask, rec, j, 16);
                    const uint4 u = *reinterpret_cast<const uint4*>(
                        in_h + (size_t)(p >> 16)*DD);
                    int row = (int)(p & 0xFFFFu);
                    bool fresh = (row != currow);
                    currow = row;
                    v.x = fresh ? u.x : hadd2_u32(v.x, u.x);
                    v.y = fresh ? u.y : hadd2_u32(v.y, u.y);
                    v.z = fresh ? u.z : hadd2_u32(v.z, u.z);
                    v.w = fresh ? u.w : hadd2_u32(v.w, u.w);
                    uint32_t* rp = sA + (currow - tile)*WP + wslot;
                    rp[0] = v.x; rp[2] = v.y; rp[4] = v.z; rp[6] = v.w;
                }
            }
            __syncwarp();   // reconverge halves before full-warp shfl below

            // post-pass: c==0 -> zero row; c>1 -> scale by 1/c (fp32)
            #pragma unroll
            for (int i = 0; i < 4; ++i) {
                int rsel = halfsel*4 + i;
                int c = __shfl_sync(0xffffffffu, offv, rsel + 1)
                      - __shfl_sync(0xffffffffu, offv, rsel);
                uint32_t* rp = sA + (grow + rsel)*WP + wslot;
                if (c == 0) {
                    rp[0] = 0u; rp[2] = 0u; rp[4] = 0u; rp[6] = 0u;
                } else if (c > 1) {
                    float inv = 1.f/(float)c;
                    float2 a0 = unpack_h2(rp[0]);
                    float2 a1 = unpack_h2(rp[2]);
                    float2 a2 = unpack_h2(rp[4]);
                    float2 a3 = unpack_h2(rp[6]);
                    rp[0] = pack_h2(a0.x*inv, a0.y*inv);
                    rp[2] = pack_h2(a1.x*inv, a1.y*inv);
                    rp[4] = pack_h2(a2.x*inv, a2.y*inv);
                    rp[6] = pack_h2(a3.x*inv, a3.y*inv);
                }
            }
        } else {
            // root chunk: direct half copy of input tile (4 rows per half)
            #pragma unroll
            for (int ii = 0; ii < 4; ++ii) {
                int rowi = grow + halfsel*4 + ii;
                int node = tile + rowi;
                uint4 u = make_uint4(0u,0u,0u,0u);
                if (node < NN)
                    u = *reinterpret_cast<const uint4*>(
                        in_h + (size_t)node*DD);
                uint32_t* rp = sA + rowi*WP + wslot;
                rp[0] = u.x; rp[2] = u.y; rp[4] = u.z; rp[6] = u.w;
            }
        }
        // pair-scoped barrier: warps w and w+8 produced rows [mrow, mrow+16)
        asm volatile("bar.sync %0, 64;" :: "r"(pbar) : "memory");

        // ================= MMA (fp16, fp32 accum) =================
        const uint32_t* sBc = (cur == 0) ? sB0 : sB1;
        #pragma unroll
        for (int k16 = 0; k16 < DD/16; ++k16) {
            const uint2 aLo = *reinterpret_cast<const uint2*>(
                &sA[(mrow + g    )*WP + k16*8 + tg*2]);   // (a0, a2)
            const uint2 aHi = *reinterpret_cast<const uint2*>(
                &sA[(mrow + g + 8)*WP + k16*8 + tg*2]);   // (a1, a3)
            #pragma unroll
            for (int n8 = 0; n8 < O2/8; ++n8) {
                const uint2 bb = *reinterpret_cast<const uint2*>(
                    &sBc[(ncol + n8*8 + g)*WP + k16*8 + tg*2]);  // (b0, b1)
                mma_f16(acc[n8][0], acc[n8][1], acc[n8][2], acc[n8][3],
                        aLo.x, aHi.x, aLo.y, aHi.y, bb.x, bb.y);
            }
        }
        cur ^= 1;
    }

    // ---- epilogue: bias (+ sigmoid), write out
    const int r0 = tile + mrow + g;
    const int r1 = r0 + 8;
    #pragma unroll
    for (int n8 = 0; n8 < O2/8; ++n8) {
        int c0 = ncol + n8*8 + 2*tg;
        int c1 = c0 + 1;
        float bz0 = bias[c0], bz1 = bias[c1];
        float v00 = acc[n8][0] + bz0;
        float v01 = acc[n8][1] + bz1;
        float v10 = acc[n8][2] + bz0;
        float v11 = acc[n8][3] + bz1;
        if (SIG) {
            v00 = 1.f/(1.f + __expf(-v00));
            v01 = 1.f/(1.f + __expf(-v01));
            v10 = 1.f/(1.f + __expf(-v10));
            v11 = 1.f/(1.f + __expf(-v11));
        }
        if (sizeof(OutT) == 2) {   // half2 pair store (c0 even)
            if (r0 < NN) *reinterpret_cast<__half2*>(
                (__half*)out + (size_t)r0*O + c0) = __floats2half2_rn(v00, v01);
            if (r1 < NN) *reinterpret_cast<__half2*>(
                (__half*)out + (size_t)r1*O + c0) = __floats2half2_rn(v10, v11);
        } else {
            if (r0 < NN) { ((float*)out)[(size_t)r0*O + c0] = v00;
                           ((float*)out)[(size_t)r0*O + c1] = v01; }
            if (r1 < NN) { ((float*)out)[(size_t)r1*O + c0] = v10;
                           ((float*)out)[(size_t)r1*O + c1] = v11; }
        }
    }
}

// ---------------- launch ----------------------------------------------------
extern "C" void kernel_launch(void* const* d_in, const int* in_sizes, int n_in,
                              void* d_out, int out_size) {
    const float* x    = (const float*)d_in[0];
    const int*   esrc = (const int*)  d_in[1];
    const int*   edst = (const int*)  d_in[2];
    const int*   etyp = (const int*)  d_in[3];
    const float* W1   = (const float*)d_in[4];
    const float* r1   = (const float*)d_in[5];
    const float* b1   = (const float*)d_in[6];
    const float* W2   = (const float*)d_in[7];
    const float* r2   = (const float*)d_in[8];
    const float* b2   = (const float*)d_in[9];
    float* out = (float*)d_out;

    constexpr int SMEM_L1 = (128 + 2*128) * 72 * 4;  // 110592 B -> 2 CTAs/SM
    constexpr int SMEM_L2 = (128 + 2* 64) * 72 * 4;  //  73728 B -> 2 CTAs/SM
    cudaFuncSetAttribute((const void*)k_layer<128,false,__half>,
                         cudaFuncAttributeMaxDynamicSharedMemorySize, SMEM_L1);
    cudaFuncSetAttribute((const void*)k_layer< 64,true ,float >,
                         cudaFuncAttributeMaxDynamicSharedMemorySize, SMEM_L2);

    void* p = nullptr;
    cudaGetSymbolAddress(&p, g_xh);  __half* xh  = (__half*)p;
    cudaGetSymbolAddress(&p, g_h);   __half* h   = (__half*)p;
    cudaGetSymbolAddress(&p, g_W1h); __half* w1h = (__half*)p;
    cudaGetSymbolAddress(&p, g_W2h); __half* w2h = (__half*)p;

    const int HB = (NE + 255)/256;
    const int T1 = ((RR+1)*DD*DD + 255)/256;
    const int T2 = ((RR+1)*64*DD + 255)/256;
    const int XC = (NN*DD/4 + 255)/256;
    k_pre    <<<HB + T1 + T2 + XC, 256>>>(edst, etyp, x, W1, r1, W2, r2); // launch 0
    k_scan   <<<NBLK,             1024>>>();                               // launch 1
    k_scatter<<<(NE+255)/256,      256>>>(esrc, edst, etyp);               // launch 2

    k_layer<128,false,__half><<<(NN+127)/128, 512, SMEM_L1>>>(xh, w1h, b1, h);   // launch 3
    k_layer< 64,true ,float ><<<(NN+127)/128, 512, SMEM_L2>>>(h,  w2h, b2, out); // launch 4
}